// round 1
// baseline (speedup 1.0000x reference)
#include <cuda_runtime.h>
#include <cstddef>

// Problem constants (match reference_code)
#define N_VARS   4096
#define WIDTH    8192
#define N_LAYERS 12
#define BATCH    1024
#define THREADS  512

// One CTA per batch row. vals vector (8192 floats) lives in dynamic SMEM,
// double-buffered (64 KB). children table is read through L1/L2 (768 KB total,
// shared by all CTAs). Bottleneck: SMEM crossbar on the random gathers.
__global__ __launch_bounds__(THREADS) void wmc_kernel(
    const float* __restrict__ weights,
    const float* __restrict__ neg_weights,
    const int2* __restrict__ children,   // [N_LAYERS][WIDTH] as int2
    float* __restrict__ out)             // [BATCH]
{
    extern __shared__ float smem[];
    float* bufA = smem;             // holds layer-even inputs / final result
    float* bufB = smem + WIDTH;

    const int b   = blockIdx.x;
    const int tid = threadIdx.x;

    // Load input row: bufA[0..4095] = weights[b], bufA[4096..8191] = neg_weights[b]
    {
        const float4* w4  = reinterpret_cast<const float4*>(weights     + (size_t)b * N_VARS);
        const float4* nw4 = reinterpret_cast<const float4*>(neg_weights + (size_t)b * N_VARS);
        float4* a4 = reinterpret_cast<float4*>(bufA);
        #pragma unroll
        for (int i = tid; i < N_VARS / 4; i += THREADS) {
            a4[i]              = w4[i];
            a4[i + N_VARS / 4] = nw4[i];
        }
    }
    __syncthreads();

    // 12 layers, alternating product (even) / sum (odd). Ping-pong buffers.
    #pragma unroll
    for (int l = 0; l < N_LAYERS; ++l) {
        const float* __restrict__ src = (l & 1) ? bufB : bufA;
        float*       __restrict__ dst = (l & 1) ? bufA : bufB;
        const int2*  __restrict__ ch  = children + (size_t)l * WIDTH;

        #pragma unroll 4
        for (int i = tid; i < WIDTH; i += THREADS) {
            int2 c = __ldg(&ch[i]);
            float x = src[c.x];
            float y = src[c.y];
            dst[i] = (l & 1) ? (x + y) : (x * y);
        }
        __syncthreads();
    }

    // After layer 11 (odd, wrote bufA): reduce bufA -> out[b]
    float acc = 0.0f;
    #pragma unroll
    for (int i = tid; i < WIDTH; i += THREADS) acc += bufA[i];

    #pragma unroll
    for (int o = 16; o > 0; o >>= 1) acc += __shfl_xor_sync(0xffffffffu, acc, o);

    __shared__ float warpsum[THREADS / 32];
    if ((tid & 31) == 0) warpsum[tid >> 5] = acc;
    __syncthreads();

    if (tid < 32) {
        acc = (tid < THREADS / 32) ? warpsum[tid] : 0.0f;
        #pragma unroll
        for (int o = 8; o > 0; o >>= 1) acc += __shfl_xor_sync(0xffffffffu, acc, o);
        if (tid == 0) out[b] = acc;
    }
}

extern "C" void kernel_launch(void* const* d_in, const int* in_sizes, int n_in,
                              void* d_out, int out_size)
{
    const float* weights     = (const float*)d_in[0];
    const float* neg_weights = (const float*)d_in[1];
    const int2*  children    = (const int2*)d_in[2];
    float* out = (float*)d_out;

    const int smem_bytes = 2 * WIDTH * sizeof(float);  // 64 KB
    cudaFuncSetAttribute(wmc_kernel, cudaFuncAttributeMaxDynamicSharedMemorySize, smem_bytes);

    wmc_kernel<<<BATCH, THREADS, smem_bytes>>>(weights, neg_weights, children, out);
}

// round 2
// speedup vs baseline: 1.3130x; 1.3130x over previous
#include <cuda_runtime.h>
#include <cstddef>

#define N_VARS   4096
#define WIDTH    8192
#define N_LAYERS 12
#define BATCH    1024
#define THREADS  512
#define BCH      4                    // batch rows per CTA (float4 lanes)
#define NODES_PER_THREAD (WIDTH / THREADS)   // 16

// One CTA per group of 4 batch rows. vals stored node-major as float4
// (4 batch rows per node) in 128KB of SMEM. Gather indices are uniform across
// the batch dimension, so each random gather is one LDS.128 serving 4 rows:
// conflict factor ~1.75x instead of ~3.3x for scalar LDS, and children LDG
// traffic is amortized 4x. Single buffer: layer outputs staged in registers,
// sync, write back in place.
__global__ __launch_bounds__(THREADS, 1) void wmc_kernel(
    const float* __restrict__ weights,
    const float* __restrict__ neg_weights,
    const int2* __restrict__ children,
    float* __restrict__ out)
{
    extern __shared__ float4 buf[];   // [WIDTH] = 8192 float4 = 128 KB

    const int g   = blockIdx.x;       // batch group (4 rows)
    const int tid = threadIdx.x;

    // ---- Load + transpose 4 rows of (weights ‖ neg_weights) into buf ----
    {
        const float* w0 = weights     + (size_t)(g * BCH + 0) * N_VARS;
        const float* w1 = weights     + (size_t)(g * BCH + 1) * N_VARS;
        const float* w2 = weights     + (size_t)(g * BCH + 2) * N_VARS;
        const float* w3 = weights     + (size_t)(g * BCH + 3) * N_VARS;
        const float* n0 = neg_weights + (size_t)(g * BCH + 0) * N_VARS;
        const float* n1 = neg_weights + (size_t)(g * BCH + 1) * N_VARS;
        const float* n2 = neg_weights + (size_t)(g * BCH + 2) * N_VARS;
        const float* n3 = neg_weights + (size_t)(g * BCH + 3) * N_VARS;
        for (int v = tid; v < N_VARS; v += THREADS) {
            buf[v]          = make_float4(__ldg(w0 + v), __ldg(w1 + v),
                                          __ldg(w2 + v), __ldg(w3 + v));
            buf[v + N_VARS] = make_float4(__ldg(n0 + v), __ldg(n1 + v),
                                          __ldg(n2 + v), __ldg(n3 + v));
        }
    }
    __syncthreads();

    // ---- Layers 0..10: gather -> regs, sync, write back in place ----
    #pragma unroll
    for (int l = 0; l < N_LAYERS - 1; ++l) {
        const int2* __restrict__ ch = children + (size_t)l * WIDTH;
        float4 r[NODES_PER_THREAD];

        #pragma unroll
        for (int k = 0; k < NODES_PER_THREAD; ++k) {
            const int node = tid + k * THREADS;
            const int2 c = __ldg(&ch[node]);
            const float4 x = buf[c.x];
            const float4 y = buf[c.y];
            if (l & 1) {
                r[k] = make_float4(x.x + y.x, x.y + y.y, x.z + y.z, x.w + y.w);
            } else {
                r[k] = make_float4(x.x * y.x, x.y * y.y, x.z * y.z, x.w * y.w);
            }
        }
        __syncthreads();
        #pragma unroll
        for (int k = 0; k < NODES_PER_THREAD; ++k) {
            buf[tid + k * THREADS] = r[k];
        }
        __syncthreads();
    }

    // ---- Layer 11 (sum layer): fold directly into the reduction ----
    float4 acc = make_float4(0.f, 0.f, 0.f, 0.f);
    {
        const int2* __restrict__ ch = children + (size_t)(N_LAYERS - 1) * WIDTH;
        #pragma unroll
        for (int k = 0; k < NODES_PER_THREAD; ++k) {
            const int2 c = __ldg(&ch[tid + k * THREADS]);
            const float4 x = buf[c.x];
            const float4 y = buf[c.y];
            acc.x += x.x + y.x;
            acc.y += x.y + y.y;
            acc.z += x.z + y.z;
            acc.w += x.w + y.w;
        }
    }

    // ---- Reduce float4 across the CTA ----
    #pragma unroll
    for (int o = 16; o > 0; o >>= 1) {
        acc.x += __shfl_xor_sync(0xffffffffu, acc.x, o);
        acc.y += __shfl_xor_sync(0xffffffffu, acc.y, o);
        acc.z += __shfl_xor_sync(0xffffffffu, acc.z, o);
        acc.w += __shfl_xor_sync(0xffffffffu, acc.w, o);
    }

    __shared__ float4 wsum[THREADS / 32];
    if ((tid & 31) == 0) wsum[tid >> 5] = acc;
    __syncthreads();

    if (tid < 32) {
        acc = (tid < THREADS / 32) ? wsum[tid] : make_float4(0.f, 0.f, 0.f, 0.f);
        #pragma unroll
        for (int o = 8; o > 0; o >>= 1) {
            acc.x += __shfl_xor_sync(0xffffffffu, acc.x, o);
            acc.y += __shfl_xor_sync(0xffffffffu, acc.y, o);
            acc.z += __shfl_xor_sync(0xffffffffu, acc.z, o);
            acc.w += __shfl_xor_sync(0xffffffffu, acc.w, o);
        }
        if (tid == 0) {
            out[g * BCH + 0] = acc.x;
            out[g * BCH + 1] = acc.y;
            out[g * BCH + 2] = acc.z;
            out[g * BCH + 3] = acc.w;
        }
    }
}

extern "C" void kernel_launch(void* const* d_in, const int* in_sizes, int n_in,
                              void* d_out, int out_size)
{
    const float* weights     = (const float*)d_in[0];
    const float* neg_weights = (const float*)d_in[1];
    const int2*  children    = (const int2*)d_in[2];
    float* out = (float*)d_out;

    const int smem_bytes = WIDTH * sizeof(float4);   // 128 KB
    cudaFuncSetAttribute(wmc_kernel, cudaFuncAttributeMaxDynamicSharedMemorySize, smem_bytes);

    wmc_kernel<<<BATCH / BCH, THREADS, smem_bytes>>>(weights, neg_weights, children, out);
}

// round 3
// speedup vs baseline: 1.3217x; 1.0066x over previous
#include <cuda_runtime.h>
#include <cstddef>

#define N_VARS   4096
#define WIDTH    8192
#define N_LAYERS 12
#define BATCH    1024
#define THREADS  1024
#define BCH      4                           // batch rows per CTA (float4 lanes)
#define NPT      (WIDTH / THREADS)           // 8 nodes per thread

// One CTA (32 warps) per group of 4 batch rows. vals node-major as float4 in
// 128KB SMEM. In-place layer update: gather->regs, bar, store, bar.
// 32 warps (vs 16 in R2) to cover LDS + children-LDG latency across barriers.
__global__ __launch_bounds__(THREADS, 1) void wmc_kernel(
    const float* __restrict__ weights,
    const float* __restrict__ neg_weights,
    const int2* __restrict__ children,
    float* __restrict__ out)
{
    extern __shared__ float4 buf[];   // [WIDTH] = 128 KB

    const int g   = blockIdx.x;
    const int tid = threadIdx.x;

    // ---- Load + transpose 4 rows of (weights ‖ neg_weights) ----
    {
        const float* w0 = weights     + (size_t)(g * BCH + 0) * N_VARS;
        const float* w1 = weights     + (size_t)(g * BCH + 1) * N_VARS;
        const float* w2 = weights     + (size_t)(g * BCH + 2) * N_VARS;
        const float* w3 = weights     + (size_t)(g * BCH + 3) * N_VARS;
        const float* n0 = neg_weights + (size_t)(g * BCH + 0) * N_VARS;
        const float* n1 = neg_weights + (size_t)(g * BCH + 1) * N_VARS;
        const float* n2 = neg_weights + (size_t)(g * BCH + 2) * N_VARS;
        const float* n3 = neg_weights + (size_t)(g * BCH + 3) * N_VARS;
        #pragma unroll
        for (int v = tid; v < N_VARS; v += THREADS) {
            buf[v]          = make_float4(__ldg(w0 + v), __ldg(w1 + v),
                                          __ldg(w2 + v), __ldg(w3 + v));
            buf[v + N_VARS] = make_float4(__ldg(n0 + v), __ldg(n1 + v),
                                          __ldg(n2 + v), __ldg(n3 + v));
        }
    }
    __syncthreads();

    // ---- Layers 0..10: gather -> regs, sync, write back in place ----
    #pragma unroll
    for (int l = 0; l < N_LAYERS - 1; ++l) {
        const int2* __restrict__ ch = children + (size_t)l * WIDTH;
        float4 r[NPT];

        #pragma unroll
        for (int k = 0; k < NPT; ++k) {
            const int2 c = __ldg(&ch[tid + k * THREADS]);
            const float4 x = buf[c.x];
            const float4 y = buf[c.y];
            if (l & 1) {
                r[k] = make_float4(x.x + y.x, x.y + y.y, x.z + y.z, x.w + y.w);
            } else {
                r[k] = make_float4(x.x * y.x, x.y * y.y, x.z * y.z, x.w * y.w);
            }
        }
        __syncthreads();
        #pragma unroll
        for (int k = 0; k < NPT; ++k) {
            buf[tid + k * THREADS] = r[k];
        }
        __syncthreads();
    }

    // ---- Layer 11 (sum layer): fold into the reduction ----
    float4 acc = make_float4(0.f, 0.f, 0.f, 0.f);
    {
        const int2* __restrict__ ch = children + (size_t)(N_LAYERS - 1) * WIDTH;
        #pragma unroll
        for (int k = 0; k < NPT; ++k) {
            const int2 c = __ldg(&ch[tid + k * THREADS]);
            const float4 x = buf[c.x];
            const float4 y = buf[c.y];
            acc.x += x.x + y.x;
            acc.y += x.y + y.y;
            acc.z += x.z + y.z;
            acc.w += x.w + y.w;
        }
    }

    // ---- CTA-wide float4 reduction ----
    #pragma unroll
    for (int o = 16; o > 0; o >>= 1) {
        acc.x += __shfl_xor_sync(0xffffffffu, acc.x, o);
        acc.y += __shfl_xor_sync(0xffffffffu, acc.y, o);
        acc.z += __shfl_xor_sync(0xffffffffu, acc.z, o);
        acc.w += __shfl_xor_sync(0xffffffffu, acc.w, o);
    }

    __shared__ float4 wsum[THREADS / 32];
    if ((tid & 31) == 0) wsum[tid >> 5] = acc;
    __syncthreads();

    if (tid < 32) {
        acc = wsum[tid];
        #pragma unroll
        for (int o = 16; o > 0; o >>= 1) {
            acc.x += __shfl_xor_sync(0xffffffffu, acc.x, o);
            acc.y += __shfl_xor_sync(0xffffffffu, acc.y, o);
            acc.z += __shfl_xor_sync(0xffffffffu, acc.z, o);
            acc.w += __shfl_xor_sync(0xffffffffu, acc.w, o);
        }
        if (tid == 0) {
            out[g * BCH + 0] = acc.x;
            out[g * BCH + 1] = acc.y;
            out[g * BCH + 2] = acc.z;
            out[g * BCH + 3] = acc.w;
        }
    }
}

extern "C" void kernel_launch(void* const* d_in, const int* in_sizes, int n_in,
                              void* d_out, int out_size)
{
    const float* weights     = (const float*)d_in[0];
    const float* neg_weights = (const float*)d_in[1];
    const int2*  children    = (const int2*)d_in[2];
    float* out = (float*)d_out;

    const int smem_bytes = WIDTH * sizeof(float4);   // 128 KB
    cudaFuncSetAttribute(wmc_kernel, cudaFuncAttributeMaxDynamicSharedMemorySize, smem_bytes);

    wmc_kernel<<<BATCH / BCH, THREADS, smem_bytes>>>(weights, neg_weights, children, out);
}

// round 5
// speedup vs baseline: 2.4724x; 1.8707x over previous
#include <cuda_runtime.h>
#include <cuda_fp16.h>
#include <cstddef>
#include <cstdint>

#define N_VARS   4096
#define WIDTH    8192
#define N_LAYERS 12
#define BATCH    1024
#define THREADS  1024
#define BCH      8                          // batch rows per CTA (8 halves = 16B/node)
#define NPT      (WIDTH / THREADS)          // 8 nodes per thread

typedef unsigned int u32;

__device__ __forceinline__ u32 h2_as_u32(__half2 h) {
    u32 r;
    __builtin_memcpy(&r, &h, 4);
    return r;
}
__device__ __forceinline__ __half2 u32_as_h2(u32 u) {
    __half2 h;
    __builtin_memcpy(&h, &u, 4);
    return h;
}
__device__ __forceinline__ u32 hmul2u(u32 a, u32 b) {
    return h2_as_u32(__hmul2(u32_as_h2(a), u32_as_h2(b)));
}
__device__ __forceinline__ u32 hadd2u(u32 a, u32 b) {
    return h2_as_u32(__hadd2(u32_as_h2(a), u32_as_h2(b)));
}

// One CTA (32 warps) per group of 8 batch rows. vals node-major as 8 halves
// (uint4, 16B) per node in 128KB SMEM -> each random gather is one LDS.128
// serving 8 evals. grid=128: single wave, all CTAs resident.
// fp16 arithmetic = one rounding per layer (same as fp32-compute+fp16-store).
__global__ __launch_bounds__(THREADS, 1) void wmc_kernel(
    const float* __restrict__ weights,
    const float* __restrict__ neg_weights,
    const int2* __restrict__ children,
    float* __restrict__ out)
{
    extern __shared__ uint4 buf[];          // [WIDTH] = 128 KB
    __shared__ float wsum[(THREADS / 32) * BCH];   // 32 warps x 8 rows

    const int g   = blockIdx.x;
    const int tid = threadIdx.x;

    // ---- Load + transpose 8 rows of (weights ‖ neg_weights), fp32 -> fp16 ----
    {
        const float* wb = weights     + (size_t)g * BCH * N_VARS;
        const float* nb = neg_weights + (size_t)g * BCH * N_VARS;
        for (int v = tid; v < N_VARS; v += THREADS) {
            __half2 w01 = __floats2half2_rn(__ldg(wb + v),            __ldg(wb + v + N_VARS));
            __half2 w23 = __floats2half2_rn(__ldg(wb + v + 2*N_VARS), __ldg(wb + v + 3*N_VARS));
            __half2 w45 = __floats2half2_rn(__ldg(wb + v + 4*N_VARS), __ldg(wb + v + 5*N_VARS));
            __half2 w67 = __floats2half2_rn(__ldg(wb + v + 6*N_VARS), __ldg(wb + v + 7*N_VARS));
            buf[v] = make_uint4(h2_as_u32(w01), h2_as_u32(w23),
                                h2_as_u32(w45), h2_as_u32(w67));

            __half2 n01 = __floats2half2_rn(__ldg(nb + v),            __ldg(nb + v + N_VARS));
            __half2 n23 = __floats2half2_rn(__ldg(nb + v + 2*N_VARS), __ldg(nb + v + 3*N_VARS));
            __half2 n45 = __floats2half2_rn(__ldg(nb + v + 4*N_VARS), __ldg(nb + v + 5*N_VARS));
            __half2 n67 = __floats2half2_rn(__ldg(nb + v + 6*N_VARS), __ldg(nb + v + 7*N_VARS));
            buf[v + N_VARS] = make_uint4(h2_as_u32(n01), h2_as_u32(n23),
                                         h2_as_u32(n45), h2_as_u32(n67));
        }
    }
    __syncthreads();

    // ---- Layers 0..10: gather -> regs, sync, write back in place ----
    #pragma unroll
    for (int l = 0; l < N_LAYERS - 1; ++l) {
        const int2* __restrict__ ch = children + (size_t)l * WIDTH;
        uint4 r[NPT];

        #pragma unroll
        for (int k = 0; k < NPT; ++k) {
            const int2 c = __ldg(&ch[tid + k * THREADS]);
            const uint4 x = buf[c.x];
            const uint4 y = buf[c.y];
            if (l & 1) {
                r[k] = make_uint4(hadd2u(x.x, y.x), hadd2u(x.y, y.y),
                                  hadd2u(x.z, y.z), hadd2u(x.w, y.w));
            } else {
                r[k] = make_uint4(hmul2u(x.x, y.x), hmul2u(x.y, y.y),
                                  hmul2u(x.z, y.z), hmul2u(x.w, y.w));
            }
        }
        __syncthreads();
        #pragma unroll
        for (int k = 0; k < NPT; ++k) {
            buf[tid + k * THREADS] = r[k];
        }
        __syncthreads();
    }

    // ---- Layer 11 (sum layer): fold into reduction, accumulate in fp32 ----
    float acc[BCH];
    #pragma unroll
    for (int j = 0; j < BCH; ++j) acc[j] = 0.0f;
    {
        const int2* __restrict__ ch = children + (size_t)(N_LAYERS - 1) * WIDTH;
        #pragma unroll
        for (int k = 0; k < NPT; ++k) {
            const int2 c = __ldg(&ch[tid + k * THREADS]);
            const uint4 x = buf[c.x];
            const uint4 y = buf[c.y];
            const u32 xs[4] = {x.x, x.y, x.z, x.w};
            const u32 ys[4] = {y.x, y.y, y.z, y.w};
            #pragma unroll
            for (int p = 0; p < 4; ++p) {
                float2 xf = __half22float2(u32_as_h2(xs[p]));
                float2 yf = __half22float2(u32_as_h2(ys[p]));
                acc[2*p + 0] += xf.x + yf.x;
                acc[2*p + 1] += xf.y + yf.y;
            }
        }
    }

    // ---- CTA-wide reduction of 8 fp32 accumulators ----
    #pragma unroll
    for (int o = 16; o > 0; o >>= 1) {
        #pragma unroll
        for (int j = 0; j < BCH; ++j)
            acc[j] += __shfl_xor_sync(0xffffffffu, acc[j], o);
    }
    if ((tid & 31) == 0) {
        #pragma unroll
        for (int j = 0; j < BCH; ++j)
            wsum[(tid >> 5) * BCH + j] = acc[j];
    }
    __syncthreads();

    if (tid < 32) {
        #pragma unroll
        for (int j = 0; j < BCH; ++j) {
            float s = wsum[tid * BCH + j];
            #pragma unroll
            for (int o = 16; o > 0; o >>= 1)
                s += __shfl_xor_sync(0xffffffffu, s, o);
            if (tid == 0) out[g * BCH + j] = s;
        }
    }
}

extern "C" void kernel_launch(void* const* d_in, const int* in_sizes, int n_in,
                              void* d_out, int out_size)
{
    const float* weights     = (const float*)d_in[0];
    const float* neg_weights = (const float*)d_in[1];
    const int2*  children    = (const int2*)d_in[2];
    float* out = (float*)d_out;

    const int smem_bytes = WIDTH * sizeof(uint4);    // 128 KB dynamic
    cudaFuncSetAttribute(wmc_kernel, cudaFuncAttributeMaxDynamicSharedMemorySize, smem_bytes);

    wmc_kernel<<<BATCH / BCH, THREADS, smem_bytes>>>(weights, neg_weights, children, out);
}